// round 1
// baseline (speedup 1.0000x reference)
#include <cuda_runtime.h>

#define N_NODES 100000
#define IN_DIM  1024
#define OUT_DIM 256
#define NNZ_X   3200000
#define NNZ_ADJ 3200000

// Scratch for xw = sparse(x) @ W  -> [N_NODES, OUT_DIM] fp32 (102.4 MB).
// __device__ global (allocation-free per harness rules).
__device__ float g_xw[(size_t)N_NODES * OUT_DIM];

// ---------------------------------------------------------------------------
// Zero a float buffer with float4 grid-stride stores.
// ---------------------------------------------------------------------------
__global__ void zero_kernel(float* __restrict__ p, int n4) {
    int i = blockIdx.x * blockDim.x + threadIdx.x;
    int stride = gridDim.x * blockDim.x;
    float4 z = make_float4(0.f, 0.f, 0.f, 0.f);
    float4* p4 = reinterpret_cast<float4*>(p);
    for (int j = i; j < n4; j += stride) p4[j] = z;
}

// ---------------------------------------------------------------------------
// COO SpMM: dst[row,:] += val * src[col,:], one warp per nnz.
// Lane t handles columns t, t+32, ..., t+224 -> each atomic instruction's 32
// lanes cover one contiguous 128B line (coalesced REDG in L2).
// ---------------------------------------------------------------------------
__global__ void __launch_bounds__(256, 8)
spmm_coo_kernel(const int* __restrict__ rows,
                const int* __restrict__ cols,
                const float* __restrict__ vals,
                const float* __restrict__ src,
                float* __restrict__ dst,
                int nnz) {
    int gwarp = (blockIdx.x * blockDim.x + threadIdx.x) >> 5;
    int lane  = threadIdx.x & 31;
    if (gwarp >= nnz) return;

    int   r = rows[gwarp];
    int   c = cols[gwarp];
    float v = vals[gwarp];

    const float* s = src + (size_t)c * OUT_DIM;
    float*       d = dst + (size_t)r * OUT_DIM;

    // Load all 8 source values first (batched LDG -> high MLP), then 8 REDs.
    float sv[OUT_DIM / 32];
#pragma unroll
    for (int j = 0; j < OUT_DIM / 32; j++)
        sv[j] = __ldg(&s[lane + 32 * j]);

#pragma unroll
    for (int j = 0; j < OUT_DIM / 32; j++)
        atomicAdd(&d[lane + 32 * j], v * sv[j]);   // return value unused -> RED
}

// ---------------------------------------------------------------------------
// In-place ReLU (float4).
// ---------------------------------------------------------------------------
__global__ void relu_kernel(float* __restrict__ p, int n4) {
    int i = blockIdx.x * blockDim.x + threadIdx.x;
    int stride = gridDim.x * blockDim.x;
    float4* p4 = reinterpret_cast<float4*>(p);
    for (int j = i; j < n4; j += stride) {
        float4 t = p4[j];
        t.x = fmaxf(t.x, 0.f);
        t.y = fmaxf(t.y, 0.f);
        t.z = fmaxf(t.z, 0.f);
        t.w = fmaxf(t.w, 0.f);
        p4[j] = t;
    }
}

// ---------------------------------------------------------------------------
// kernel_launch: inputs in metadata order:
//   0: x_rows (int32, NNZ_X)    1: x_cols (int32)   2: x_values (f32)
//   3: adj_rows (int32)         4: adj_cols (int32) 5: adj_values (f32)
//   6: W (f32, IN_DIM*OUT_DIM)
// Output: f32 [N_NODES, OUT_DIM]
// ---------------------------------------------------------------------------
extern "C" void kernel_launch(void* const* d_in, const int* in_sizes, int n_in,
                              void* d_out, int out_size) {
    const int*   x_rows   = (const int*)  d_in[0];
    const int*   x_cols   = (const int*)  d_in[1];
    const float* x_vals   = (const float*)d_in[2];
    const int*   adj_rows = (const int*)  d_in[3];
    const int*   adj_cols = (const int*)  d_in[4];
    const float* adj_vals = (const float*)d_in[5];
    const float* W        = (const float*)d_in[6];
    float*       out      = (float*)d_out;

    float* xw = nullptr;
    cudaGetSymbolAddress((void**)&xw, g_xw);

    const int n_elems = N_NODES * OUT_DIM;       // 25.6M floats
    const int n4      = n_elems / 4;

    // 1. zero xw and out (out is poisoned by harness)
    zero_kernel<<<2048, 256>>>(xw, n4);
    zero_kernel<<<2048, 256>>>(out, n4);

    // 2. SpMM1: xw = sparse(x) @ W
    {
        int warps  = NNZ_X;
        int blocks = (warps * 32 + 255) / 256;
        spmm_coo_kernel<<<blocks, 256>>>(x_rows, x_cols, x_vals, W, xw, NNZ_X);
    }

    // 3. SpMM2: out = sparse(adj) @ xw
    {
        int warps  = NNZ_ADJ;
        int blocks = (warps * 32 + 255) / 256;
        spmm_coo_kernel<<<blocks, 256>>>(adj_rows, adj_cols, adj_vals, xw, out, NNZ_ADJ);
    }

    // 4. ReLU in place on out
    relu_kernel<<<2048, 256>>>(out, n4);
}

// round 2
// speedup vs baseline: 2.1752x; 2.1752x over previous
#include <cuda_runtime.h>

#define N_NODES 100000
#define IN_DIM  1024
#define OUT_DIM 256
#define NNZ_X   3200000
#define NNZ_ADJ 3200000

#define SCAN_B   1024
#define N_SCANBLK ((N_NODES + SCAN_B - 1) / SCAN_B)   // 98

// ---------------- scratch (__device__ globals; no allocs allowed) ----------
__device__ float g_xw[(size_t)N_NODES * OUT_DIM];      // 102.4 MB

__device__ int   g_counts_x[N_NODES];
__device__ int   g_counts_a[N_NODES];
__device__ int   g_fill_x[N_NODES];
__device__ int   g_fill_a[N_NODES];
__device__ int   g_offs_x[N_NODES + 1];
__device__ int   g_offs_a[N_NODES + 1];
__device__ int   g_bsums_x[N_SCANBLK];
__device__ int   g_bsums_a[N_SCANBLK];
__device__ int   g_ccol_x[NNZ_X];
__device__ float g_cval_x[NNZ_X];
__device__ int   g_ccol_a[NNZ_ADJ];
__device__ float g_cval_a[NNZ_ADJ];

// ---------------- zero 4 int arrays of N_NODES each ------------------------
__global__ void zero4_kernel(int* a, int* b, int* c, int* d) {
    int i = blockIdx.x * blockDim.x + threadIdx.x;
    int stride = gridDim.x * blockDim.x;
    for (int j = i; j < N_NODES; j += stride) {
        a[j] = 0; b[j] = 0; c[j] = 0; d[j] = 0;
    }
}

// ---------------- histogram of row indices ---------------------------------
__global__ void hist_kernel(const int* __restrict__ rows, int* __restrict__ counts, int nnz) {
    int i = blockIdx.x * blockDim.x + threadIdx.x;
    if (i < nnz) atomicAdd(&counts[rows[i]], 1);
}

// ---------------- scan pass A: per-block exclusive scan --------------------
__global__ void scanA_kernel(const int* __restrict__ counts,
                             int* __restrict__ offs,
                             int* __restrict__ bsums) {
    __shared__ int sm[SCAN_B];
    int t = threadIdx.x;
    int i = blockIdx.x * SCAN_B + t;
    int v = (i < N_NODES) ? counts[i] : 0;
    sm[t] = v;
    __syncthreads();
    // Hillis-Steele inclusive scan
    for (int d = 1; d < SCAN_B; d <<= 1) {
        int add = (t >= d) ? sm[t - d] : 0;
        __syncthreads();
        sm[t] += add;
        __syncthreads();
    }
    int incl = sm[t];
    if (i < N_NODES) offs[i] = incl - v;           // exclusive
    if (t == SCAN_B - 1) bsums[blockIdx.x] = incl; // block total
}

// ---------------- scan pass B: serial exclusive scan of block sums ---------
__global__ void scanB_kernel(int* bsums, int nb) {
    if (threadIdx.x == 0 && blockIdx.x == 0) {
        int run = 0;
        for (int i = 0; i < nb; i++) { int v = bsums[i]; bsums[i] = run; run += v; }
    }
}

// ---------------- scan pass C: add block offsets ---------------------------
__global__ void scanC_kernel(int* __restrict__ offs, const int* __restrict__ bsums, int total) {
    int i = blockIdx.x * SCAN_B + threadIdx.x;
    if (i < N_NODES) offs[i] += bsums[blockIdx.x];
    if (i == 0) offs[N_NODES] = total;
}

// ---------------- scatter into CSR -----------------------------------------
__global__ void scatter_kernel(const int* __restrict__ rows,
                               const int* __restrict__ cols,
                               const float* __restrict__ vals,
                               const int* __restrict__ offs,
                               int* __restrict__ fill,
                               int* __restrict__ ccol,
                               float* __restrict__ cval,
                               int nnz) {
    int i = blockIdx.x * blockDim.x + threadIdx.x;
    if (i >= nnz) return;
    int r = rows[i];
    int p = offs[r] + atomicAdd(&fill[r], 1);
    ccol[p] = cols[i];
    cval[p] = vals[i];
}

// ---------------- CSR SpMM: one warp per row -------------------------------
// acc[j] over lanes covers 256 output columns; each output row written once.
template <bool RELU>
__global__ void __launch_bounds__(256, 8)
csr_spmm_kernel(const int* __restrict__ offs,
                const int* __restrict__ ccol,
                const float* __restrict__ cval,
                const float* __restrict__ src,
                float* __restrict__ dst) {
    int warp = (blockIdx.x * blockDim.x + threadIdx.x) >> 5;
    int lane = threadIdx.x & 31;
    if (warp >= N_NODES) return;

    int beg = offs[warp];
    int end = offs[warp + 1];

    float acc[OUT_DIM / 32];
#pragma unroll
    for (int j = 0; j < OUT_DIM / 32; j++) acc[j] = 0.f;

    for (int base = beg; base < end; base += 32) {
        int k = base + lane;
        int   c = 0;
        float v = 0.f;
        if (k < end) { c = ccol[k]; v = cval[k]; }
        int m = min(32, end - base);
        for (int t = 0; t < m; t++) {
            int   cc = __shfl_sync(0xffffffffu, c, t);
            float vv = __shfl_sync(0xffffffffu, v, t);
            const float* s = src + (size_t)cc * OUT_DIM;
#pragma unroll
            for (int j = 0; j < OUT_DIM / 32; j++)
                acc[j] = fmaf(vv, __ldg(&s[lane + 32 * j]), acc[j]);
        }
    }

    float* d = dst + (size_t)warp * OUT_DIM;
#pragma unroll
    for (int j = 0; j < OUT_DIM / 32; j++) {
        float r = acc[j];
        if (RELU) r = fmaxf(r, 0.f);
        d[lane + 32 * j] = r;
    }
}

// ---------------------------------------------------------------------------
extern "C" void kernel_launch(void* const* d_in, const int* in_sizes, int n_in,
                              void* d_out, int out_size) {
    const int*   x_rows   = (const int*)  d_in[0];
    const int*   x_cols   = (const int*)  d_in[1];
    const float* x_vals   = (const float*)d_in[2];
    const int*   adj_rows = (const int*)  d_in[3];
    const int*   adj_cols = (const int*)  d_in[4];
    const float* adj_vals = (const float*)d_in[5];
    const float* W        = (const float*)d_in[6];
    float*       out      = (float*)d_out;

    float *xw; int *counts_x, *counts_a, *fill_x, *fill_a, *offs_x, *offs_a;
    int *bsums_x, *bsums_a, *ccol_x, *ccol_a; float *cval_x, *cval_a;
    cudaGetSymbolAddress((void**)&xw,       g_xw);
    cudaGetSymbolAddress((void**)&counts_x, g_counts_x);
    cudaGetSymbolAddress((void**)&counts_a, g_counts_a);
    cudaGetSymbolAddress((void**)&fill_x,   g_fill_x);
    cudaGetSymbolAddress((void**)&fill_a,   g_fill_a);
    cudaGetSymbolAddress((void**)&offs_x,   g_offs_x);
    cudaGetSymbolAddress((void**)&offs_a,   g_offs_a);
    cudaGetSymbolAddress((void**)&bsums_x,  g_bsums_x);
    cudaGetSymbolAddress((void**)&bsums_a,  g_bsums_a);
    cudaGetSymbolAddress((void**)&ccol_x,   g_ccol_x);
    cudaGetSymbolAddress((void**)&cval_x,   g_cval_x);
    cudaGetSymbolAddress((void**)&ccol_a,   g_ccol_a);
    cudaGetSymbolAddress((void**)&cval_a,   g_cval_a);

    const int nnz_blocks = (NNZ_X + 255) / 256;

    // 1. zero counters
    zero4_kernel<<<512, 256>>>(counts_x, counts_a, fill_x, fill_a);

    // 2. histograms
    hist_kernel<<<nnz_blocks, 256>>>(x_rows,   counts_x, NNZ_X);
    hist_kernel<<<nnz_blocks, 256>>>(adj_rows, counts_a, NNZ_ADJ);

    // 3. scans -> row offsets
    scanA_kernel<<<N_SCANBLK, SCAN_B>>>(counts_x, offs_x, bsums_x);
    scanA_kernel<<<N_SCANBLK, SCAN_B>>>(counts_a, offs_a, bsums_a);
    scanB_kernel<<<1, 32>>>(bsums_x, N_SCANBLK);
    scanB_kernel<<<1, 32>>>(bsums_a, N_SCANBLK);
    scanC_kernel<<<N_SCANBLK, SCAN_B>>>(offs_x, bsums_x, NNZ_X);
    scanC_kernel<<<N_SCANBLK, SCAN_B>>>(offs_a, bsums_a, NNZ_ADJ);

    // 4. scatter COO -> CSR
    scatter_kernel<<<nnz_blocks, 256>>>(x_rows, x_cols, x_vals,
                                        offs_x, fill_x, ccol_x, cval_x, NNZ_X);
    scatter_kernel<<<nnz_blocks, 256>>>(adj_rows, adj_cols, adj_vals,
                                        offs_a, fill_a, ccol_a, cval_a, NNZ_ADJ);

    // 5. SpMM1: xw = sparse(x) @ W        (W is L2-resident)
    const int spmm_blocks = (N_NODES * 32 + 255) / 256;
    csr_spmm_kernel<false><<<spmm_blocks, 256>>>(offs_x, ccol_x, cval_x, W, xw);

    // 6. SpMM2 + ReLU: out = relu(sparse(adj) @ xw)
    csr_spmm_kernel<true><<<spmm_blocks, 256>>>(offs_a, ccol_a, cval_a, xw, out);
}